// round 2
// baseline (speedup 1.0000x reference)
#include <cuda_runtime.h>

#define THREADS 256
#define NWARP (THREADS / 32)
#define TOPK 5
#define NCAT 8
#define FULLM 0xffffffffu
#define L2E 1.4426950408889634f
#define LN2 0.6931471805599453f
#define NEG_INF (-__int_as_float(0x7f800000))

__device__ float g_rowloss[8192];

__device__ __forceinline__ float ex2f(float x) {
    float y; asm("ex2.approx.ftz.f32 %0, %1;" : "=f"(y) : "f"(x)); return y;
}
__device__ __forceinline__ float lg2f(float x) {
    float y; asm("lg2.approx.ftz.f32 %0, %1;" : "=f"(y) : "f"(x)); return y;
}

__device__ __forceinline__ void insert5(float (&tv)[TOPK], int (&ti)[TOPK], float v, int idx) {
    tv[TOPK - 1] = v; ti[TOPK - 1] = idx;
#pragma unroll
    for (int k = TOPK - 1; k > 0; --k) {
        if (tv[k] > tv[k - 1]) {
            float tf = tv[k]; tv[k] = tv[k - 1]; tv[k - 1] = tf;
            int   tt = ti[k]; ti[k] = ti[k - 1]; ti[k - 1] = tt;
        }
    }
}

__global__ void __launch_bounds__(THREADS)
hier_loss_rows(const float* __restrict__ logits,
               const int* __restrict__ labels,
               const int* __restrict__ catlab,
               const int* __restrict__ c2c,
               int V, int ncmd)
{
    const int b    = blockIdx.x;
    const int tid  = threadIdx.x;
    const int lane = tid & 31;
    const int w    = tid >> 5;
    const float* row = logits + (size_t)b * (size_t)V;

    __shared__ int   s_c2c[64];
    __shared__ float s_wC[NWARP], s_wS[NWARP];
    __shared__ float s_wTv[NWARP][TOPK];
    __shared__ int   s_wTi[NWARP][TOPK];
    __shared__ float s_cat[NCAT];

    if (tid < 64 && tid < ncmd) s_c2c[tid] = c2c[tid];

    // warp-replicated top-5 (identical across all lanes of a warp)
    float tv[TOPK]; int ti[TOPK];
#pragma unroll
    for (int k = 0; k < TOPK; ++k) { tv[k] = NEG_INF; ti[k] = 0; }

    // fixed-base log2-domain softmax accumulation
    float x0   = __ldg(row);                  // same base for all threads in block
    float negC = -x0 * L2E;
    float s0 = 0.f, s1 = 0.f, s2 = 0.f, s3 = 0.f;

    // alignment peel: row base may be misaligned to 16B
    const int mis = (int)(((size_t)b * (size_t)V) & 3);
    const int pre = (4 - mis) & 3;
    const int nv4 = (V - pre) >> 2;                 // aligned float4 count
    const int nIterV = nv4 / (4 * THREADS);
    const int vecElems = nIterV * 16 * THREADS;     // elements covered by vector loop
    const float4* __restrict__ p4 =
        (const float4*)(row + pre) + (w << 5) + lane;

    // ---- head (pre <= 3 elements, one masked full-warp step) ----
    {
        bool valid = (tid < pre);
        float x = valid ? __ldg(row + tid) : NEG_INF;
        float d = fmaf(x, L2E, negC);
        s0 += ex2f(d);
        unsigned bal = __ballot_sync(FULLM, x > tv[TOPK - 1]);
        while (bal) {
            int L = __ffs(bal) - 1; bal &= bal - 1;
            float xv = __shfl_sync(FULLM, x, L);
            if (xv > tv[TOPK - 1]) insert5(tv, ti, xv, (w << 5) + L);
        }
    }

    // ---- main vector loop: 4 x float4 = 16 elements / thread / iter ----
    int jbase = 0;  // float4 index base for this iteration
    for (int j = 0; j < nIterV; ++j) {
        float4 v0 = __ldg(p4);
        float4 v1 = __ldg(p4 + THREADS);
        float4 v2 = __ldg(p4 + 2 * THREADS);
        float4 v3 = __ldg(p4 + 3 * THREADS);
        p4 += 4 * THREADS;

        float xs[16] = { v0.x, v0.y, v0.z, v0.w,  v1.x, v1.y, v1.z, v1.w,
                         v2.x, v2.y, v2.z, v2.w,  v3.x, v3.y, v3.z, v3.w };

        // sum of ex2 in d-domain
        float d0  = fmaf(xs[0],  L2E, negC), d1  = fmaf(xs[1],  L2E, negC);
        float d2  = fmaf(xs[2],  L2E, negC), d3  = fmaf(xs[3],  L2E, negC);
        float d4  = fmaf(xs[4],  L2E, negC), d5  = fmaf(xs[5],  L2E, negC);
        float d6  = fmaf(xs[6],  L2E, negC), d7  = fmaf(xs[7],  L2E, negC);
        float d8  = fmaf(xs[8],  L2E, negC), d9  = fmaf(xs[9],  L2E, negC);
        float d10 = fmaf(xs[10], L2E, negC), d11 = fmaf(xs[11], L2E, negC);
        float d12 = fmaf(xs[12], L2E, negC), d13 = fmaf(xs[13], L2E, negC);
        float d14 = fmaf(xs[14], L2E, negC), d15 = fmaf(xs[15], L2E, negC);
        s0 += ex2f(d0);  s1 += ex2f(d1);  s2 += ex2f(d2);  s3 += ex2f(d3);
        s0 += ex2f(d4);  s1 += ex2f(d5);  s2 += ex2f(d6);  s3 += ex2f(d7);
        s0 += ex2f(d8);  s1 += ex2f(d9);  s2 += ex2f(d10); s3 += ex2f(d11);
        s0 += ex2f(d12); s1 += ex2f(d13); s2 += ex2f(d14); s3 += ex2f(d15);

        // x-domain max for top-k filter + rebase guard
        float m0 = fmaxf(fmaxf(xs[0],  xs[1]),  fmaxf(xs[2],  xs[3]));
        float m1 = fmaxf(fmaxf(xs[4],  xs[5]),  fmaxf(xs[6],  xs[7]));
        float m2 = fmaxf(fmaxf(xs[8],  xs[9]),  fmaxf(xs[10], xs[11]));
        float m3 = fmaxf(fmaxf(xs[12], xs[13]), fmaxf(xs[14], xs[15]));
        float mx = fmaxf(fmaxf(m0, m1), fmaxf(m2, m3));

        // rare rebase (never fires for N(0,1) inputs)
        if (fmaf(mx, L2E, negC) > 60.0f) {
            float dm = fmaf(mx, L2E, negC);
            float sc = ex2f(-dm);
            s0 *= sc; s1 *= sc; s2 *= sc; s3 *= sc;
            negC -= dm;
        }

        unsigned bal = __ballot_sync(FULLM, mx > tv[TOPK - 1]);
        if (bal) {
            do {
                int L = __ffs(bal) - 1; bal &= bal - 1;
#pragma unroll
                for (int q4 = 0; q4 < 4; ++q4) {
#pragma unroll
                    for (int qe = 0; qe < 4; ++qe) {
                        float xv = __shfl_sync(FULLM, xs[q4 * 4 + qe], L);
                        if (xv > tv[TOPK - 1]) {
                            int f4idx = jbase + q4 * THREADS + (w << 5) + L;
                            insert5(tv, ti, xv, pre + f4idx * 4 + qe);
                        }
                    }
                }
            } while (bal);
        }
        jbase += 4 * THREADS;
    }

    // ---- scalar tail: [pre + vecElems, V) ----
    for (int i0 = pre + vecElems; i0 < V; i0 += THREADS) {
        int i = i0 + tid;
        bool valid = (i < V);
        float x = valid ? __ldg(row + i) : NEG_INF;
        float d = fmaf(x, L2E, negC);
        s0 += ex2f(d);
        unsigned bal = __ballot_sync(FULLM, x > tv[TOPK - 1]);
        while (bal) {
            int L = __ffs(bal) - 1; bal &= bal - 1;
            float xv = __shfl_sync(FULLM, x, L);
            if (xv > tv[TOPK - 1]) insert5(tv, ti, xv, i0 + (w << 5) + L);
        }
    }

    // ---- warp reduce (C, s) ----
    float s = (s0 + s1) + (s2 + s3);
    float C = -negC;
#pragma unroll
    for (int off = 16; off; off >>= 1) {
        float Co = __shfl_xor_sync(FULLM, C, off);
        float so = __shfl_xor_sync(FULLM, s, off);
        float Cn = fmaxf(C, Co);
        s = s * ex2f(C - Cn) + so * ex2f(Co - Cn);
        C = Cn;
    }

    if (lane == 0) {
        s_wC[w] = C; s_wS[w] = s;
#pragma unroll
        for (int k = 0; k < TOPK; ++k) { s_wTv[w][k] = tv[k]; s_wTi[w][k] = ti[k]; }
    }
    __syncthreads();

    if (tid == 0) {
        float Cf = s_wC[0], sf = s_wS[0];
        for (int ww = 1; ww < NWARP; ++ww) {
            float Co = s_wC[ww], so = s_wS[ww];
            float Cn = fmaxf(Cf, Co);
            sf = sf * ex2f(Cf - Cn) + so * ex2f(Co - Cn);
            Cf = Cn;
        }
        float ftv[TOPK]; int fti[TOPK];
#pragma unroll
        for (int k = 0; k < TOPK; ++k) { ftv[k] = s_wTv[0][k]; fti[k] = s_wTi[0][k]; }
        for (int ww = 1; ww < NWARP; ++ww) {
            for (int k = 0; k < TOPK; ++k) {
                float v = s_wTv[ww][k];
                if (v > ftv[TOPK - 1]) insert5(ftv, fti, v, s_wTi[ww][k]);
                else break;
            }
        }

        float lse  = (Cf + lg2f(sf)) * LN2;
        int   lab  = __ldg(labels + b);
        float xlab = __ldg(row + lab);
        float nll_cmd = lse - xlab;

#pragma unroll
        for (int c = 0; c < NCAT; ++c) s_cat[c] = 0.0f;
#pragma unroll
        for (int k = 0; k < TOPK; ++k)
            s_cat[s_c2c[fti[k] % ncmd]] += ftv[k];

        float mxc = s_cat[0];
#pragma unroll
        for (int c = 1; c < NCAT; ++c) mxc = fmaxf(mxc, s_cat[c]);
        float ssum = 0.0f;
#pragma unroll
        for (int c = 0; c < NCAT; ++c) ssum += ex2f((s_cat[c] - mxc) * L2E);
        int   cl = __ldg(catlab + b);
        float nll_cat = lg2f(ssum) * LN2 + mxc - s_cat[cl];

        g_rowloss[b] = 0.6f * nll_cmd + 0.4f * nll_cat;
    }
}

__global__ void __launch_bounds__(256)
hier_loss_finalize(float* __restrict__ out, int B)
{
    __shared__ float sh[256];
    int tid = threadIdx.x;
    float a = 0.0f;
    for (int i = tid; i < B; i += 256) a += g_rowloss[i];
    sh[tid] = a;
    __syncthreads();
#pragma unroll
    for (int off = 128; off; off >>= 1) {
        if (tid < off) sh[tid] += sh[tid + off];
        __syncthreads();
    }
    if (tid == 0) out[0] = sh[0] * (1.0f / (float)B);
}

extern "C" void kernel_launch(void* const* d_in, const int* in_sizes, int n_in,
                              void* d_out, int out_size)
{
    const float* logits = (const float*)d_in[0];
    const int*   labels = (const int*)d_in[1];
    const int*   catlab = (const int*)d_in[2];
    const int*   c2c    = (const int*)d_in[3];

    const int B    = in_sizes[1];
    const int V    = in_sizes[0] / B;
    const int ncmd = in_sizes[3];

    hier_loss_rows<<<B, THREADS>>>(logits, labels, catlab, c2c, V, ncmd);
    hier_loss_finalize<<<1, 256>>>((float*)d_out, B);
}

// round 3
// speedup vs baseline: 1.8981x; 1.8981x over previous
#include <cuda_runtime.h>

#define THREADS 256
#define NWARP (THREADS / 32)
#define TOPK 5
#define NCAT 8
#define FULLM 0xffffffffu
#define L2E 1.4426950408889634f
#define LN2 0.6931471805599453f
#define NEG_INF (-__int_as_float(0x7f800000))

__device__ float g_rowloss[8192];
__device__ unsigned int g_done = 0;

__device__ __forceinline__ float ex2f(float x) {
    float y; asm("ex2.approx.ftz.f32 %0, %1;" : "=f"(y) : "f"(x)); return y;
}
__device__ __forceinline__ float lg2f(float x) {
    float y; asm("lg2.approx.ftz.f32 %0, %1;" : "=f"(y) : "f"(x)); return y;
}

__device__ __forceinline__ void insert5(float (&tv)[TOPK], int (&ti)[TOPK], float v, int idx) {
    tv[TOPK - 1] = v; ti[TOPK - 1] = idx;
#pragma unroll
    for (int k = TOPK - 1; k > 0; --k) {
        if (tv[k] > tv[k - 1]) {
            float tf = tv[k]; tv[k] = tv[k - 1]; tv[k - 1] = tf;
            int   tt = ti[k]; ti[k] = ti[k - 1]; ti[k - 1] = tt;
        }
    }
}

__global__ void __launch_bounds__(THREADS)
hier_loss_fused(const float* __restrict__ logits,
                const int* __restrict__ labels,
                const int* __restrict__ catlab,
                const int* __restrict__ c2c,
                float* __restrict__ out,
                int V, int ncmd, int B)
{
    const int b    = blockIdx.x;
    const int tid  = threadIdx.x;
    const int lane = tid & 31;
    const int w    = tid >> 5;
    const float* row = logits + (size_t)b * (size_t)V;

    __shared__ int   s_c2c[64];
    __shared__ float s_wC[NWARP], s_wS[NWARP];
    __shared__ float s_wTv[NWARP][TOPK];
    __shared__ int   s_wTi[NWARP][TOPK];
    __shared__ float s_cat[NCAT];
    __shared__ int   s_isLast;
    __shared__ float s_red[THREADS];

    if (tid < 64 && tid < ncmd) s_c2c[tid] = c2c[tid];

    // warp-replicated top-5 (identical across lanes of a warp)
    float tv[TOPK]; int ti[TOPK];
#pragma unroll
    for (int k = 0; k < TOPK; ++k) { tv[k] = NEG_INF; ti[k] = 0; }

    // fixed-base log2-domain softmax accumulation
    float x0   = __ldg(row);
    float negC = -x0 * L2E;
    float s0 = 0.f, s1 = 0.f, s2 = 0.f, s3 = 0.f;

    // alignment peel: row base may be misaligned to 16B
    const int mis = (int)(((size_t)b * (size_t)V) & 3);
    const int pre = (4 - mis) & 3;
    const int nv4 = (V - pre) >> 2;
    const int nIterV = nv4 / (4 * THREADS);
    const int vecElems = nIterV * 16 * THREADS;
    const float4* __restrict__ p4 = (const float4*)(row + pre) + tid;

    // ---- head (pre <= 3 elements, one masked full-warp step) ----
    {
        bool valid = (tid < pre);
        float x = valid ? __ldg(row + tid) : NEG_INF;
        float d = fmaf(x, L2E, negC);
        s0 += ex2f(d);
        unsigned bal = __ballot_sync(FULLM, x > tv[TOPK - 1]);
        while (bal) {
            int L = __ffs(bal) - 1; bal &= bal - 1;
            float xv = __shfl_sync(FULLM, x, L);
            if (xv > tv[TOPK - 1]) insert5(tv, ti, xv, (w << 5) + L);
        }
    }

    // per-quad processing: fresh threshold, 4-shfl insert path
#define QUAD(v, f4off)                                                        \
    do {                                                                      \
        float d0 = fmaf((v).x, L2E, negC), d1 = fmaf((v).y, L2E, negC);       \
        float d2 = fmaf((v).z, L2E, negC), d3 = fmaf((v).w, L2E, negC);       \
        s0 += ex2f(d0); s1 += ex2f(d1); s2 += ex2f(d2); s3 += ex2f(d3);       \
        float qm = fmaxf(fmaxf((v).x, (v).y), fmaxf((v).z, (v).w));           \
        itermax = fmaxf(itermax, qm);                                         \
        unsigned bal = __ballot_sync(FULLM, qm > tv[TOPK - 1]);               \
        while (bal) {                                                         \
            int L = __ffs(bal) - 1; bal &= bal - 1;                           \
            float a0 = __shfl_sync(FULLM, (v).x, L);                          \
            float a1 = __shfl_sync(FULLM, (v).y, L);                          \
            float a2 = __shfl_sync(FULLM, (v).z, L);                          \
            float a3 = __shfl_sync(FULLM, (v).w, L);                          \
            int bi = pre + 4 * ((f4off) + (w << 5) + L);                      \
            if (a0 > tv[TOPK - 1]) insert5(tv, ti, a0, bi + 0);               \
            if (a1 > tv[TOPK - 1]) insert5(tv, ti, a1, bi + 1);               \
            if (a2 > tv[TOPK - 1]) insert5(tv, ti, a2, bi + 2);               \
            if (a3 > tv[TOPK - 1]) insert5(tv, ti, a3, bi + 3);               \
        }                                                                     \
    } while (0)

    // ---- main vector loop: 4 x float4 = 16 elements / thread / iter ----
    int jbase = 0;
    for (int j = 0; j < nIterV; ++j) {
        float4 v0 = __ldg(p4);
        float4 v1 = __ldg(p4 + THREADS);
        float4 v2 = __ldg(p4 + 2 * THREADS);
        float4 v3 = __ldg(p4 + 3 * THREADS);
        p4 += 4 * THREADS;

        float itermax = NEG_INF;
        QUAD(v0, jbase);
        QUAD(v1, jbase + THREADS);
        QUAD(v2, jbase + 2 * THREADS);
        QUAD(v3, jbase + 3 * THREADS);

        // rare rebase (never fires for N(0,1) inputs)
        float dm = fmaf(itermax, L2E, negC);
        if (dm > 60.0f) {
            float sc = ex2f(-dm);
            s0 *= sc; s1 *= sc; s2 *= sc; s3 *= sc;
            negC -= dm;
        }
        jbase += 4 * THREADS;
    }
#undef QUAD

    // ---- scalar tail: [pre + vecElems, V) ----
    for (int i0 = pre + vecElems; i0 < V; i0 += THREADS) {
        int i = i0 + tid;
        bool valid = (i < V);
        float x = valid ? __ldg(row + i) : NEG_INF;
        float d = fmaf(x, L2E, negC);
        s0 += ex2f(d);
        unsigned bal = __ballot_sync(FULLM, x > tv[TOPK - 1]);
        while (bal) {
            int L = __ffs(bal) - 1; bal &= bal - 1;
            float xv = __shfl_sync(FULLM, x, L);
            if (xv > tv[TOPK - 1]) insert5(tv, ti, xv, i0 + (w << 5) + L);
        }
    }

    // ---- warp reduce (C, s) ----
    float s = (s0 + s1) + (s2 + s3);
    float C = -negC;
#pragma unroll
    for (int off = 16; off; off >>= 1) {
        float Co = __shfl_xor_sync(FULLM, C, off);
        float so = __shfl_xor_sync(FULLM, s, off);
        float Cn = fmaxf(C, Co);
        s = s * ex2f(C - Cn) + so * ex2f(Co - Cn);
        C = Cn;
    }

    if (lane == 0) {
        s_wC[w] = C; s_wS[w] = s;
#pragma unroll
        for (int k = 0; k < TOPK; ++k) { s_wTv[w][k] = tv[k]; s_wTi[w][k] = ti[k]; }
    }
    __syncthreads();

    if (tid == 0) {
        float Cf = s_wC[0], sf = s_wS[0];
        for (int ww = 1; ww < NWARP; ++ww) {
            float Co = s_wC[ww], so = s_wS[ww];
            float Cn = fmaxf(Cf, Co);
            sf = sf * ex2f(Cf - Cn) + so * ex2f(Co - Cn);
            Cf = Cn;
        }
        float ftv[TOPK]; int fti[TOPK];
#pragma unroll
        for (int k = 0; k < TOPK; ++k) { ftv[k] = s_wTv[0][k]; fti[k] = s_wTi[0][k]; }
        for (int ww = 1; ww < NWARP; ++ww) {
            for (int k = 0; k < TOPK; ++k) {
                float v = s_wTv[ww][k];
                if (v > ftv[TOPK - 1]) insert5(ftv, fti, v, s_wTi[ww][k]);
                else break;
            }
        }

        float lse  = (Cf + lg2f(sf)) * LN2;
        int   lab  = __ldg(labels + b);
        float xlab = __ldg(row + lab);
        float nll_cmd = lse - xlab;

#pragma unroll
        for (int c = 0; c < NCAT; ++c) s_cat[c] = 0.0f;
#pragma unroll
        for (int k = 0; k < TOPK; ++k)
            s_cat[s_c2c[fti[k] % ncmd]] += ftv[k];

        float mxc = s_cat[0];
#pragma unroll
        for (int c = 1; c < NCAT; ++c) mxc = fmaxf(mxc, s_cat[c]);
        float ssum = 0.0f;
#pragma unroll
        for (int c = 0; c < NCAT; ++c) ssum += ex2f((s_cat[c] - mxc) * L2E);
        int   cl = __ldg(catlab + b);
        float nll_cat = lg2f(ssum) * LN2 + mxc - s_cat[cl];

        g_rowloss[b] = 0.6f * nll_cmd + 0.4f * nll_cat;

        // last-block-done protocol
        __threadfence();
        unsigned int prev = atomicAdd(&g_done, 1u);
        s_isLast = (prev == (unsigned int)(gridDim.x - 1));
    }
    __syncthreads();

    // ---- fused final reduction (deterministic: single block, fixed order) ----
    if (s_isLast) {
        __threadfence();   // acquire: all g_rowloss writes visible
        float a = 0.0f;
        for (int i = tid; i < B; i += THREADS) a += g_rowloss[i];
        s_red[tid] = a;
        __syncthreads();
#pragma unroll
        for (int off = THREADS / 2; off; off >>= 1) {
            if (tid < off) s_red[tid] += s_red[tid + off];
            __syncthreads();
        }
        if (tid == 0) {
            out[0] = s_red[0] * (1.0f / (float)B);
            atomicExch(&g_done, 0u);   // reset for next graph replay
        }
    }
}

extern "C" void kernel_launch(void* const* d_in, const int* in_sizes, int n_in,
                              void* d_out, int out_size)
{
    const float* logits = (const float*)d_in[0];
    const int*   labels = (const int*)d_in[1];
    const int*   catlab = (const int*)d_in[2];
    const int*   c2c    = (const int*)d_in[3];

    const int B    = in_sizes[1];
    const int V    = in_sizes[0] / B;
    const int ncmd = in_sizes[3];

    hier_loss_fused<<<B, THREADS>>>(logits, labels, catlab, c2c,
                                    (float*)d_out, V, ncmd, B);
}